// round 14
// baseline (speedup 1.0000x reference)
#include <cuda_runtime.h>
#include <cuda_fp16.h>
#include <cstdint>

#define DIN      512
#define DHID     2048
#define NMAX     200000
#define TILE_M   64
#define NCHUNK   128
#define NCHUNKS  (DHID / NCHUNK)         // 16
#define KTILE    64
#define NKT      (DIN / KTILE)           // 8
#define NTILES   (NCHUNKS * NKT)         // 128
#define THREADS  128
#define A_BYTES  (TILE_M * DIN * 2)      // 65536
#define WB_BYTES 4096                    // per-warp B tile: 32 rows x 64 halfs x 2B
#define NBUF     3
#define B_REGION (4 * NBUF * WB_BYTES)   // 49152
#define ACC_OFF  (A_BYTES + B_REGION)    // 114688
#define SMEM_TOTAL (ACC_OFF + TILE_M * 4)  // 114944 (~112.3KB, 2 CTAs/SM)

__device__ __half g_W1h[3u * DHID * DIN];
__device__ int    g_idx[3 * NMAX];
__device__ int    g_cnt[3];
__device__ int    g_is64;

// ---------------- PTX helpers (sm_80+ baseline features only) ----------------
__device__ __forceinline__ uint32_t smem_u32(const void* p) {
    uint32_t a;
    asm("{ .reg .u64 t; cvta.to.shared.u64 t, %1; cvt.u32.u64 %0, t; }" : "=r"(a) : "l"(p));
    return a;
}
#define LDSM_X4(r0, r1, r2, r3, addr) \
    asm volatile("ldmatrix.sync.aligned.m8n8.x4.shared.b16 {%0,%1,%2,%3}, [%4];" \
        : "=r"(r0), "=r"(r1), "=r"(r2), "=r"(r3) : "r"(addr))
#define MMA16816(d, a, b) \
    asm volatile("mma.sync.aligned.m16n8k16.row.col.f32.f16.f16.f32 " \
        "{%0,%1,%2,%3}, {%4,%5,%6,%7}, {%8,%9}, {%0,%1,%2,%3};" \
        : "+f"((d)[0]), "+f"((d)[1]), "+f"((d)[2]), "+f"((d)[3]) \
        : "r"((a)[0]), "r"((a)[1]), "r"((a)[2]), "r"((a)[3]), \
          "r"((b)[0]), "r"((b)[1]))
#define CP_ASYNC16(dst, src) \
    asm volatile("cp.async.cg.shared.global [%0], [%1], 16;" :: "r"(dst), "l"(src))
#define CP_COMMIT()  asm volatile("cp.async.commit_group;" ::: "memory")
#define CP_WAIT2()   asm volatile("cp.async.wait_group 2;" ::: "memory")

// ---------------- prep kernels ----------------
__global__ void prep_kernel(const int* an_words) {
    if (threadIdx.x == 0) {
        g_cnt[0] = 0; g_cnt[1] = 0; g_cnt[2] = 0;
        int s = 1;
        for (int i = 1; i < 64; i += 2)
            if (an_words[i] != 0) { s = 0; break; }
        g_is64 = s;  // int64 values in [0,10) => all odd 32-bit words zero
    }
}

__global__ void route_kernel(const int* an, int n) {
    int i = blockIdx.x * blockDim.x + threadIdx.x;
    if (i >= n) return;
    int v = an[g_is64 ? (2 * i) : i];
    int r = (v == 6) ? 0 : (v == 1) ? 1 : 2;
    int p = atomicAdd(&g_cnt[r], 1);
    g_idx[r * NMAX + p] = i;
}

__global__ void convw_kernel(const float* __restrict__ cw, const float* __restrict__ hw,
                             const float* __restrict__ ow) {
    int i = blockIdx.x * blockDim.x + threadIdx.x;
    if (i >= DHID * DIN) return;
    g_W1h[i]                  = __float2half_rn(cw[i]);
    g_W1h[DHID * DIN + i]     = __float2half_rn(hw[i]);
    g_W1h[2 * DHID * DIN + i] = __float2half_rn(ow[i]);
}

// ------- fused routed MLP (HMMA, 2 CTAs/SM, warp-private, batched frags) -------
__global__ void __launch_bounds__(THREADS, 2)
fused_mlp_kernel(const float* __restrict__ x, float* __restrict__ out,
                 const float* b1_0, const float* b1_1, const float* b1_2,
                 const float* w2_0, const float* w2_1, const float* w2_2,
                 const float* b2_0, const float* b2_1, const float* b2_2) {
    int route = blockIdx.y;
    int cnt = g_cnt[route];
    int tile0 = blockIdx.x * TILE_M;
    if (tile0 >= cnt) return;

    extern __shared__ char smem[];
    uint32_t sb = smem_u32(smem);
    float* accbuf = (float*)(smem + ACC_OFF);
    int tid  = threadIdx.x;
    int lane = tid & 31;
    int wid  = tid >> 5;         // 0..3 = wN (each warp: 64 M x 32 N)

    const int*    idx = g_idx + route * NMAX;
    const __half* Wb  = g_W1h + (size_t)route * DHID * DIN;
    const float*  b1  = (route == 0) ? b1_0 : (route == 1) ? b1_1 : b1_2;
    const float*  w2  = (route == 0) ? w2_0 : (route == 1) ? w2_1 : w2_2;
    const float*  b2  = (route == 0) ? b2_0 : (route == 1) ? b2_1 : b2_2;

    uint32_t wbBase = sb + A_BYTES + (uint32_t)wid * (NBUF * WB_BYTES);

    // ---- warp-private B tile cp.async: 32 n-rows x 64 k halfs = 4KB ----
    auto issueTileW = [&](int t) {
        int n = t >> 3, kt = t & 7;
        const __half* src0 = Wb + (size_t)(n * NCHUNK + wid * 32) * DIN + kt * KTILE;
        uint32_t bbase = wbBase + (uint32_t)(t % NBUF) * WB_BYTES;
#pragma unroll
        for (int i = 0; i < 8; i++) {
            int u  = lane + i * 32;     // 0..255 16B units
            int hr = u >> 3;            // local n-row 0..31
            int ku = u & 7;             // 16B unit within 128B row
            const __half* src = src0 + (size_t)hr * DIN + ku * 8;
            uint32_t dst = bbase + hr * 128 + (((uint32_t)ku * 16) ^ (((uint32_t)hr & 7) << 4));
            CP_ASYNC16(dst, src);
        }
        CP_COMMIT();
    };

    issueTileW(0); issueTileW(1);

    // ---- A gather: 64 rows x 512 fp32 -> fp16, swizzled SMEM (cooperative) ----
#pragma unroll
    for (int i = 0; i < 32; i++) {
        int u   = tid + i * THREADS;    // 0..4095 16B units
        int row = u >> 6;               // 0..63
        int ku  = u & 63;
        int g   = tile0 + row;
        int src = idx[(g < cnt) ? g : (cnt - 1)];
        const float4* xp = (const float4*)(x + (size_t)src * DIN) + ku * 2;
        float4 v0 = __ldg(xp);
        float4 v1 = __ldg(xp + 1);
        __half2 h0 = __floats2half2_rn(v0.x, v0.y);
        __half2 h1 = __floats2half2_rn(v0.z, v0.w);
        __half2 h2 = __floats2half2_rn(v1.x, v1.y);
        __half2 h3 = __floats2half2_rn(v1.z, v1.w);
        uint4 pk;
        pk.x = *reinterpret_cast<uint32_t*>(&h0);
        pk.y = *reinterpret_cast<uint32_t*>(&h1);
        pk.z = *reinterpret_cast<uint32_t*>(&h2);
        pk.w = *reinterpret_cast<uint32_t*>(&h3);
        uint32_t off = (uint32_t)row * 1024 + (((uint32_t)ku * 16) ^ (((uint32_t)row & 7) << 4));
        *reinterpret_cast<uint4*>(smem + off) = pk;
    }
    if (tid < TILE_M) accbuf[tid] = 0.f;
    __syncthreads();   // publishes A tile + accbuf; the ONLY barrier before the end

    // ---- main loop: barrier-free, per-kt batched fragments ----
    float partial[8];
#pragma unroll
    for (int i = 0; i < 8; i++) partial[i] = 0.f;
    uint32_t afr[64];   // all A frags for one kt: [ks][mt][q] = afr[ks*16+mt*4+q]
    uint32_t bfr[32];   // all B frags for one kt: [ks][nt][q2] = bfr[ks*8+nt*2+q2]

    for (int n = 0; n < NCHUNKS; n++) {
        float acc[4][4][4];
#pragma unroll
        for (int mt = 0; mt < 4; mt++)
#pragma unroll
            for (int nt = 0; nt < 4; nt++)
#pragma unroll
                for (int q = 0; q < 4; q++) acc[mt][nt][q] = 0.f;

        for (int kt = 0; kt < NKT; kt++) {
            int t = n * NKT + kt;
            if (t + 2 < NTILES) issueTileW(t + 2);
            else CP_COMMIT();                 // uniform group accounting

            // batched A frag load: 16 x4 LDSM, independent, before the wait
#pragma unroll
            for (int ks = 0; ks < 4; ks++) {
#pragma unroll
                for (int mt = 0; mt < 4; mt++) {
                    int arow = mt * 16 + (lane & 15);
                    uint32_t abyte = (uint32_t)(kt * 128 + ks * 32 + (lane >> 4) * 16);
                    uint32_t aaddr = sb + (uint32_t)arow * 1024 +
                                     (abyte ^ (((uint32_t)arow & 7) << 4));
                    uint32_t* a = &afr[ks * 16 + mt * 4];
                    LDSM_X4(a[0], a[1], a[2], a[3], aaddr);
                }
            }

            CP_WAIT2();                       // tile t complete (t+1,t+2 pending)
            __syncwarp();
            uint32_t bbase = wbBase + (uint32_t)(t % NBUF) * WB_BYTES;

            // batched B frag load: 8 x4 LDSM
#pragma unroll
            for (int ks = 0; ks < 4; ks++) {
                int nt0  = (lane >> 4) & 1;
                uint32_t bbyte = (uint32_t)(ks * 32 + ((lane >> 3) & 1) * 16);
                int nrow = nt0 * 8 + (lane & 7);
                uint32_t baddr = bbase + (uint32_t)nrow * 128 +
                                 (bbyte ^ (((uint32_t)nrow & 7) << 4));
                uint32_t* b = &bfr[ks * 8];
                LDSM_X4(b[0], b[1], b[2], b[3], baddr);
                int nrow2 = 16 + nt0 * 8 + (lane & 7);
                uint32_t baddr2 = bbase + (uint32_t)nrow2 * 128 +
                                  (bbyte ^ (((uint32_t)nrow2 & 7) << 4));
                LDSM_X4(b[4], b[5], b[6], b[7], baddr2);
            }

            // 64 MMAs back-to-back
#pragma unroll
            for (int ks = 0; ks < 4; ks++)
#pragma unroll
                for (int mt = 0; mt < 4; mt++)
#pragma unroll
                    for (int nt = 0; nt < 4; nt++)
                        MMA16816(acc[mt][nt], &afr[ks * 16 + mt * 4],
                                 &bfr[ks * 8 + nt * 2]);
        }

        // ---- per-chunk epilogue fold: relu(d + b1) * w2 ----
        int cbase = n * NCHUNK + wid * 32;
#pragma unroll
        for (int nt = 0; nt < 4; nt++) {
            int c0 = cbase + nt * 8 + (lane & 3) * 2;
            float2 bb = __ldg((const float2*)(b1 + c0));
            float2 ww = __ldg((const float2*)(w2 + c0));
#pragma unroll
            for (int mt = 0; mt < 4; mt++) {
#pragma unroll
                for (int half = 0; half < 2; half++) {
                    float d0 = acc[mt][nt][half * 2 + 0];
                    float d1 = acc[mt][nt][half * 2 + 1];
                    partial[mt * 2 + half] += fmaxf(d0 + bb.x, 0.f) * ww.x
                                            + fmaxf(d1 + bb.y, 0.f) * ww.y;
                }
            }
        }
    }

    // ---- cross-warp combine ----
#pragma unroll
    for (int mt = 0; mt < 4; mt++) {
#pragma unroll
        for (int half = 0; half < 2; half++) {
            float s = partial[mt * 2 + half];
            s += __shfl_xor_sync(0xFFFFFFFFu, s, 1);
            s += __shfl_xor_sync(0xFFFFFFFFu, s, 2);
            if ((lane & 3) == 0) {
                int r = mt * 16 + half * 8 + (lane >> 2);
                atomicAdd(&accbuf[r], s);
            }
        }
    }
    __syncthreads();

    // ---- scatter ----
    if (tid < TILE_M) {
        int g = tile0 + tid;
        if (g < cnt) out[idx[g]] = accbuf[tid] + __ldg(b2);
    }
}

// ---------------- launch ----------------
extern "C" void kernel_launch(void* const* d_in, const int* in_sizes, int n_in,
                              void* d_out, int out_size) {
    const float* x   = (const float*)d_in[0];
    const int*   an  = (const int*)d_in[1];
    const float* cW1 = (const float*)d_in[2];
    const float* cb1 = (const float*)d_in[3];
    const float* cW2 = (const float*)d_in[4];
    const float* cb2 = (const float*)d_in[5];
    const float* hW1 = (const float*)d_in[6];
    const float* hb1 = (const float*)d_in[7];
    const float* hW2 = (const float*)d_in[8];
    const float* hb2 = (const float*)d_in[9];
    const float* oW1 = (const float*)d_in[10];
    const float* ob1 = (const float*)d_in[11];
    const float* oW2 = (const float*)d_in[12];
    const float* ob2 = (const float*)d_in[13];
    float* out = (float*)d_out;

    int n = in_sizes[0] / DIN;

    prep_kernel<<<1, 1>>>(an);
    route_kernel<<<(n + 255) / 256, 256>>>(an, n);
    convw_kernel<<<(DHID * DIN + 255) / 256, 256>>>(cW1, hW1, oW1);

    cudaFuncSetAttribute(fused_mlp_kernel,
                         cudaFuncAttributeMaxDynamicSharedMemorySize, SMEM_TOTAL);

    int tiles = (n + TILE_M - 1) / TILE_M;
    dim3 grid(tiles, 3);
    fused_mlp_kernel<<<grid, THREADS, SMEM_TOTAL>>>(
        x, out, cb1, hb1, ob1, cW2, hW2, oW2, cb2, hb2, ob2);
}

// round 15
// speedup vs baseline: 1.1200x; 1.1200x over previous
#include <cuda_runtime.h>
#include <cuda_fp16.h>
#include <cstdint>

#define DIN      512
#define DHID     2048
#define NMAX     200000
#define TILE_M   64
#define NCHUNK   128
#define NCHUNKS  (DHID / NCHUNK)         // 16
#define KTILE    64
#define NKT      (DIN / KTILE)           // 8
#define NTILES   (NCHUNKS * NKT)         // 128
#define THREADS  128
#define A_BYTES  (TILE_M * DIN * 2)      // 65536
#define WB_BYTES 4096                    // per-warp B tile: 32 rows x 64 halfs x 2B
#define NBUF     3
#define B_REGION (4 * NBUF * WB_BYTES)   // 49152
#define ACC_OFF  (A_BYTES + B_REGION)    // 114688
#define SMEM_TOTAL (ACC_OFF + TILE_M * 4)  // 114944 (~112.3KB, 2 CTAs/SM)

__device__ __half g_W1h[3u * DHID * DIN];
__device__ int    g_idx[3 * NMAX];
__device__ int    g_cnt[3];
__device__ int    g_is64;

// ---------------- PTX helpers (sm_80+ baseline features only) ----------------
__device__ __forceinline__ uint32_t smem_u32(const void* p) {
    uint32_t a;
    asm("{ .reg .u64 t; cvta.to.shared.u64 t, %1; cvt.u32.u64 %0, t; }" : "=r"(a) : "l"(p));
    return a;
}
#define LDSM_X4(r0, r1, r2, r3, addr) \
    asm volatile("ldmatrix.sync.aligned.m8n8.x4.shared.b16 {%0,%1,%2,%3}, [%4];" \
        : "=r"(r0), "=r"(r1), "=r"(r2), "=r"(r3) : "r"(addr))
#define MMA16816(d, a, b) \
    asm volatile("mma.sync.aligned.m16n8k16.row.col.f32.f16.f16.f32 " \
        "{%0,%1,%2,%3}, {%4,%5,%6,%7}, {%8,%9}, {%0,%1,%2,%3};" \
        : "+f"((d)[0]), "+f"((d)[1]), "+f"((d)[2]), "+f"((d)[3]) \
        : "r"((a)[0]), "r"((a)[1]), "r"((a)[2]), "r"((a)[3]), \
          "r"((b)[0]), "r"((b)[1]))
#define CP_ASYNC16(dst, src) \
    asm volatile("cp.async.cg.shared.global [%0], [%1], 16;" :: "r"(dst), "l"(src))
#define CP_COMMIT()  asm volatile("cp.async.commit_group;" ::: "memory")
#define CP_WAIT2()   asm volatile("cp.async.wait_group 2;" ::: "memory")

// ---------------- prep kernels ----------------
__global__ void prep_kernel(const int* an_words) {
    if (threadIdx.x == 0) {
        g_cnt[0] = 0; g_cnt[1] = 0; g_cnt[2] = 0;
        int s = 1;
        for (int i = 1; i < 64; i += 2)
            if (an_words[i] != 0) { s = 0; break; }
        g_is64 = s;  // int64 values in [0,10) => all odd 32-bit words zero
    }
}

// block-aggregated routing: SMEM histogram + one global atomic per route per CTA
__global__ void route_kernel(const int* an, int n) {
    __shared__ int s_cnt[3];
    __shared__ int s_base[3];
    int tid = threadIdx.x;
    int i = blockIdx.x * blockDim.x + tid;
    if (tid < 3) s_cnt[tid] = 0;
    __syncthreads();
    int r = -1, p = 0;
    if (i < n) {
        int v = an[g_is64 ? (2 * i) : i];
        r = (v == 6) ? 0 : (v == 1) ? 1 : 2;
        p = atomicAdd(&s_cnt[r], 1);
    }
    __syncthreads();
    if (tid < 3) s_base[tid] = atomicAdd(&g_cnt[tid], s_cnt[tid]);
    __syncthreads();
    if (r >= 0) g_idx[r * NMAX + s_base[r] + p] = i;
}

__global__ void convw_kernel(const float* __restrict__ cw, const float* __restrict__ hw,
                             const float* __restrict__ ow) {
    int i = blockIdx.x * blockDim.x + threadIdx.x;
    if (i >= DHID * DIN) return;
    g_W1h[i]                  = __float2half_rn(cw[i]);
    g_W1h[DHID * DIN + i]     = __float2half_rn(hw[i]);
    g_W1h[2 * DHID * DIN + i] = __float2half_rn(ow[i]);
}

// ------- fused routed MLP (HMMA, 2 CTAs/SM, warp-private B pipeline) -------
__global__ void __launch_bounds__(THREADS, 2)
fused_mlp_kernel(const float* __restrict__ x, float* __restrict__ out,
                 const float* b1_0, const float* b1_1, const float* b1_2,
                 const float* w2_0, const float* w2_1, const float* w2_2,
                 const float* b2_0, const float* b2_1, const float* b2_2) {
    int route = blockIdx.y;
    int cnt = g_cnt[route];
    int tile0 = blockIdx.x * TILE_M;
    if (tile0 >= cnt) return;

    extern __shared__ char smem[];
    uint32_t sb = smem_u32(smem);
    float* accbuf = (float*)(smem + ACC_OFF);
    int tid  = threadIdx.x;
    int lane = tid & 31;
    int wid  = tid >> 5;         // 0..3 = wN (each warp: 64 M x 32 N)

    const int*    idx = g_idx + route * NMAX;
    const __half* Wb  = g_W1h + (size_t)route * DHID * DIN;
    const float*  b1  = (route == 0) ? b1_0 : (route == 1) ? b1_1 : b1_2;
    const float*  w2  = (route == 0) ? w2_0 : (route == 1) ? w2_1 : w2_2;
    const float*  b2  = (route == 0) ? b2_0 : (route == 1) ? b2_1 : b2_2;

    uint32_t wbBase = sb + A_BYTES + (uint32_t)wid * (NBUF * WB_BYTES);

    // ---- warp-private B tile cp.async: 32 n-rows x 64 k halfs = 4KB ----
    auto issueTileW = [&](int t) {
        int n = t >> 3, kt = t & 7;
        const __half* src0 = Wb + (size_t)(n * NCHUNK + wid * 32) * DIN + kt * KTILE;
        uint32_t bbase = wbBase + (uint32_t)(t % NBUF) * WB_BYTES;
#pragma unroll
        for (int i = 0; i < 8; i++) {
            int u  = lane + i * 32;     // 0..255 16B units
            int hr = u >> 3;            // local n-row 0..31
            int ku = u & 7;             // 16B unit within 128B row
            const __half* src = src0 + (size_t)hr * DIN + ku * 8;
            uint32_t dst = bbase + hr * 128 + (((uint32_t)ku * 16) ^ (((uint32_t)hr & 7) << 4));
            CP_ASYNC16(dst, src);
        }
        CP_COMMIT();
    };

    issueTileW(0); issueTileW(1);

    // ---- A gather: 64 rows x 512 fp32 -> fp16, swizzled SMEM (cooperative) ----
#pragma unroll
    for (int i = 0; i < 32; i++) {
        int u   = tid + i * THREADS;    // 0..4095 16B units
        int row = u >> 6;               // 0..63
        int ku  = u & 63;
        int g   = tile0 + row;
        int src = idx[(g < cnt) ? g : (cnt - 1)];
        const float4* xp = (const float4*)(x + (size_t)src * DIN) + ku * 2;
        float4 v0 = __ldg(xp);
        float4 v1 = __ldg(xp + 1);
        __half2 h0 = __floats2half2_rn(v0.x, v0.y);
        __half2 h1 = __floats2half2_rn(v0.z, v0.w);
        __half2 h2 = __floats2half2_rn(v1.x, v1.y);
        __half2 h3 = __floats2half2_rn(v1.z, v1.w);
        uint4 pk;
        pk.x = *reinterpret_cast<uint32_t*>(&h0);
        pk.y = *reinterpret_cast<uint32_t*>(&h1);
        pk.z = *reinterpret_cast<uint32_t*>(&h2);
        pk.w = *reinterpret_cast<uint32_t*>(&h3);
        uint32_t off = (uint32_t)row * 1024 + (((uint32_t)ku * 16) ^ (((uint32_t)row & 7) << 4));
        *reinterpret_cast<uint4*>(smem + off) = pk;
    }
    if (tid < TILE_M) accbuf[tid] = 0.f;
    __syncthreads();   // publishes A tile + accbuf; the ONLY barrier before the end

    // ---- fragment load helpers ----
    auto loadA = [&](int kt, int ks, uint32_t* a) {
#pragma unroll
        for (int mt = 0; mt < 4; mt++) {
            int arow = mt * 16 + (lane & 15);
            uint32_t abyte = (uint32_t)(kt * 128 + ks * 32 + (lane >> 4) * 16);
            uint32_t aaddr = sb + (uint32_t)arow * 1024 +
                             (abyte ^ (((uint32_t)arow & 7) << 4));
            LDSM_X4(a[mt * 4 + 0], a[mt * 4 + 1], a[mt * 4 + 2], a[mt * 4 + 3], aaddr);
        }
    };
    auto loadB = [&](uint32_t bbase, int ks, uint32_t* b) {
        int nt0  = (lane >> 4) & 1;
        int nrow = nt0 * 8 + (lane & 7);
        uint32_t bbyte = (uint32_t)(ks * 32 + ((lane >> 3) & 1) * 16);
        uint32_t baddr = bbase + (uint32_t)nrow * 128 +
                         (bbyte ^ (((uint32_t)nrow & 7) << 4));
        uint32_t r0, r1, r2, r3;
        LDSM_X4(r0, r1, r2, r3, baddr);
        b[0] = r0; b[1] = r1; b[2] = r2; b[3] = r3;
        int nrow2 = 16 + nt0 * 8 + (lane & 7);
        uint32_t baddr2 = bbase + (uint32_t)nrow2 * 128 +
                          (bbyte ^ (((uint32_t)nrow2 & 7) << 4));
        LDSM_X4(r0, r1, r2, r3, baddr2);
        b[4] = r0; b[5] = r1; b[6] = r2; b[7] = r3;
    };

    // ---- main loop: barrier-free, warp-private pipeline ----
    float partial[8];
#pragma unroll
    for (int i = 0; i < 8; i++) partial[i] = 0.f;
    uint32_t afr[16];     // A frags [mt*4+q]
    uint32_t bfr[2][8];   // B frags double buffer [buf][nt*2+q]

    for (int n = 0; n < NCHUNKS; n++) {
        float acc[4][4][4];
#pragma unroll
        for (int mt = 0; mt < 4; mt++)
#pragma unroll
            for (int nt = 0; nt < 4; nt++)
#pragma unroll
                for (int q = 0; q < 4; q++) acc[mt][nt][q] = 0.f;

        for (int kt = 0; kt < NKT; kt++) {
            int t = n * NKT + kt;
            if (t + 2 < NTILES) issueTileW(t + 2);
            else CP_COMMIT();                 // uniform group accounting
            loadA(kt, 0, afr);                // A is stable; overlap with wait
            CP_WAIT2();                       // tile t complete (t+1,t+2 pending)
            __syncwarp();

            uint32_t bbase = wbBase + (uint32_t)(t % NBUF) * WB_BYTES;
            loadB(bbase, 0, bfr[0]);
#pragma unroll
            for (int ks = 0; ks < 4; ks++) {
                int cur = ks & 1, nxt = cur ^ 1;
                if (ks < 3) loadB(bbase, ks + 1, bfr[nxt]);
#pragma unroll
                for (int mt = 0; mt < 4; mt++)
#pragma unroll
                    for (int nt = 0; nt < 4; nt++)
                        MMA16816(acc[mt][nt], &afr[mt * 4], &bfr[cur][nt * 2]);
                if (ks < 3) loadA(kt, ks + 1, afr);
            }
        }

        // ---- per-chunk epilogue fold: relu(d + b1) * w2 ----
        int cbase = n * NCHUNK + wid * 32;
#pragma unroll
        for (int nt = 0; nt < 4; nt++) {
            int c0 = cbase + nt * 8 + (lane & 3) * 2;
            float2 bb = __ldg((const float2*)(b1 + c0));
            float2 ww = __ldg((const float2*)(w2 + c0));
#pragma unroll
            for (int mt = 0; mt < 4; mt++) {
#pragma unroll
                for (int half = 0; half < 2; half++) {
                    float d0 = acc[mt][nt][half * 2 + 0];
                    float d1 = acc[mt][nt][half * 2 + 1];
                    partial[mt * 2 + half] += fmaxf(d0 + bb.x, 0.f) * ww.x
                                            + fmaxf(d1 + bb.y, 0.f) * ww.y;
                }
            }
        }
    }

    // ---- cross-warp combine ----
#pragma unroll
    for (int mt = 0; mt < 4; mt++) {
#pragma unroll
        for (int half = 0; half < 2; half++) {
            float s = partial[mt * 2 + half];
            s += __shfl_xor_sync(0xFFFFFFFFu, s, 1);
            s += __shfl_xor_sync(0xFFFFFFFFu, s, 2);
            if ((lane & 3) == 0) {
                int r = mt * 16 + half * 8 + (lane >> 2);
                atomicAdd(&accbuf[r], s);
            }
        }
    }
    __syncthreads();

    // ---- scatter ----
    if (tid < TILE_M) {
        int g = tile0 + tid;
        if (g < cnt) out[idx[g]] = accbuf[tid] + __ldg(b2);
    }
}

// ---------------- launch ----------------
extern "C" void kernel_launch(void* const* d_in, const int* in_sizes, int n_in,
                              void* d_out, int out_size) {
    const float* x   = (const float*)d_in[0];
    const int*   an  = (const int*)d_in[1];
    const float* cW1 = (const float*)d_in[2];
    const float* cb1 = (const float*)d_in[3];
    const float* cW2 = (const float*)d_in[4];
    const float* cb2 = (const float*)d_in[5];
    const float* hW1 = (const float*)d_in[6];
    const float* hb1 = (const float*)d_in[7];
    const float* hW2 = (const float*)d_in[8];
    const float* hb2 = (const float*)d_in[9];
    const float* oW1 = (const float*)d_in[10];
    const float* ob1 = (const float*)d_in[11];
    const float* oW2 = (const float*)d_in[12];
    const float* ob2 = (const float*)d_in[13];
    float* out = (float*)d_out;

    int n = in_sizes[0] / DIN;

    prep_kernel<<<1, 1>>>(an);
    route_kernel<<<(n + 255) / 256, 256>>>(an, n);
    convw_kernel<<<(DHID * DIN + 255) / 256, 256>>>(cW1, hW1, oW1);

    cudaFuncSetAttribute(fused_mlp_kernel,
                         cudaFuncAttributeMaxDynamicSharedMemorySize, SMEM_TOTAL);

    int tiles = (n + TILE_M - 1) / TILE_M;
    dim3 grid(tiles, 3);
    fused_mlp_kernel<<<grid, THREADS, SMEM_TOTAL>>>(
        x, out, cb1, hb1, ob1, cW2, hW2, oW2, cb2, hb2, ob2);
}

// round 16
// speedup vs baseline: 1.1358x; 1.0141x over previous
#include <cuda_runtime.h>
#include <cuda_fp16.h>
#include <cstdint>

#define DIN      512
#define DHID     2048
#define NMAX     200000
#define TILE_M   64
#define NCHUNK   128
#define NCHUNKS  (DHID / NCHUNK)         // 16
#define KTILE    64
#define NKT      (DIN / KTILE)           // 8
#define NTILES   (NCHUNKS * NKT)         // 128
#define THREADS  128
#define A_BYTES  (TILE_M * DIN * 2)      // 65536
#define WB_BYTES 4096                    // per-warp B tile: 32 rows x 64 halfs x 2B
#define NBUF     3
#define B_REGION (4 * NBUF * WB_BYTES)   // 49152
#define ACC_OFF  (A_BYTES + B_REGION)    // 114688
#define SMEM_TOTAL (ACC_OFF + TILE_M * 4)  // 114944 (~112.3KB, 2 CTAs/SM)

__device__ __half g_W1h[3u * DHID * DIN];
__device__ int    g_idx[3 * NMAX];
__device__ int    g_cnt[3];
__device__ int    g_is64;

// ---------------- PTX helpers (sm_80+ baseline features only) ----------------
__device__ __forceinline__ uint32_t smem_u32(const void* p) {
    uint32_t a;
    asm("{ .reg .u64 t; cvta.to.shared.u64 t, %1; cvt.u32.u64 %0, t; }" : "=r"(a) : "l"(p));
    return a;
}
#define LDSM_X4(r0, r1, r2, r3, addr) \
    asm volatile("ldmatrix.sync.aligned.m8n8.x4.shared.b16 {%0,%1,%2,%3}, [%4];" \
        : "=r"(r0), "=r"(r1), "=r"(r2), "=r"(r3) : "r"(addr))
#define MMA16816(d, a, b) \
    asm volatile("mma.sync.aligned.m16n8k16.row.col.f32.f16.f16.f32 " \
        "{%0,%1,%2,%3}, {%4,%5,%6,%7}, {%8,%9}, {%0,%1,%2,%3};" \
        : "+f"((d)[0]), "+f"((d)[1]), "+f"((d)[2]), "+f"((d)[3]) \
        : "r"((a)[0]), "r"((a)[1]), "r"((a)[2]), "r"((a)[3]), \
          "r"((b)[0]), "r"((b)[1]))
#define CP_ASYNC16(dst, src) \
    asm volatile("cp.async.cg.shared.global [%0], [%1], 16;" :: "r"(dst), "l"(src))
#define CP_COMMIT()  asm volatile("cp.async.commit_group;" ::: "memory")
#define CP_WAIT1()   asm volatile("cp.async.wait_group 1;" ::: "memory")

// ---------------- prep kernels ----------------
__global__ void prep_kernel(const int* an_words) {
    if (threadIdx.x == 0) {
        g_cnt[0] = 0; g_cnt[1] = 0; g_cnt[2] = 0;
        int s = 1;
        for (int i = 1; i < 64; i += 2)
            if (an_words[i] != 0) { s = 0; break; }
        g_is64 = s;  // int64 values in [0,10) => all odd 32-bit words zero
    }
}

// block-aggregated routing: SMEM histogram + one global atomic per route per CTA
__global__ void route_kernel(const int* an, int n) {
    __shared__ int s_cnt[3];
    __shared__ int s_base[3];
    int tid = threadIdx.x;
    int i = blockIdx.x * blockDim.x + tid;
    if (tid < 3) s_cnt[tid] = 0;
    __syncthreads();
    int r = -1, p = 0;
    if (i < n) {
        int v = an[g_is64 ? (2 * i) : i];
        r = (v == 6) ? 0 : (v == 1) ? 1 : 2;
        p = atomicAdd(&s_cnt[r], 1);
    }
    __syncthreads();
    if (tid < 3) s_base[tid] = atomicAdd(&g_cnt[tid], s_cnt[tid]);
    __syncthreads();
    if (r >= 0) g_idx[r * NMAX + s_base[r] + p] = i;
}

__global__ void convw_kernel(const float* __restrict__ cw, const float* __restrict__ hw,
                             const float* __restrict__ ow) {
    int i = blockIdx.x * blockDim.x + threadIdx.x;
    if (i >= DHID * DIN) return;
    g_W1h[i]                  = __float2half_rn(cw[i]);
    g_W1h[DHID * DIN + i]     = __float2half_rn(hw[i]);
    g_W1h[2 * DHID * DIN + i] = __float2half_rn(ow[i]);
}

// ------- fused routed MLP (HMMA, 2 CTAs/SM, cross-kt prefetched pipeline) -------
__global__ void __launch_bounds__(THREADS, 2)
fused_mlp_kernel(const float* __restrict__ x, float* __restrict__ out,
                 const float* b1_0, const float* b1_1, const float* b1_2,
                 const float* w2_0, const float* w2_1, const float* w2_2,
                 const float* b2_0, const float* b2_1, const float* b2_2) {
    int route = blockIdx.y;
    int cnt = g_cnt[route];
    int tile0 = blockIdx.x * TILE_M;
    if (tile0 >= cnt) return;

    extern __shared__ char smem[];
    uint32_t sb = smem_u32(smem);
    float* accbuf = (float*)(smem + ACC_OFF);
    int tid  = threadIdx.x;
    int lane = tid & 31;
    int wid  = tid >> 5;         // 0..3 = wN (each warp: 64 M x 32 N)

    const int*    idx = g_idx + route * NMAX;
    const __half* Wb  = g_W1h + (size_t)route * DHID * DIN;
    const float*  b1  = (route == 0) ? b1_0 : (route == 1) ? b1_1 : b1_2;
    const float*  w2  = (route == 0) ? w2_0 : (route == 1) ? w2_1 : w2_2;
    const float*  b2  = (route == 0) ? b2_0 : (route == 1) ? b2_1 : b2_2;

    uint32_t wbBase = sb + A_BYTES + (uint32_t)wid * (NBUF * WB_BYTES);

    // ---- warp-private B tile cp.async: 32 n-rows x 64 k halfs = 4KB ----
    auto issueTileW = [&](int t) {
        int n = t >> 3, kt = t & 7;
        const __half* src0 = Wb + (size_t)(n * NCHUNK + wid * 32) * DIN + kt * KTILE;
        uint32_t bbase = wbBase + (uint32_t)(t % NBUF) * WB_BYTES;
#pragma unroll
        for (int i = 0; i < 8; i++) {
            int u  = lane + i * 32;     // 0..255 16B units
            int hr = u >> 3;            // local n-row 0..31
            int ku = u & 7;             // 16B unit within 128B row
            const __half* src = src0 + (size_t)hr * DIN + ku * 8;
            uint32_t dst = bbase + hr * 128 + (((uint32_t)ku * 16) ^ (((uint32_t)hr & 7) << 4));
            CP_ASYNC16(dst, src);
        }
        CP_COMMIT();
    };

    issueTileW(0); issueTileW(1);

    // ---- A gather: 64 rows x 512 fp32 -> fp16, swizzled SMEM (cooperative) ----
#pragma unroll
    for (int i = 0; i < 32; i++) {
        int u   = tid + i * THREADS;    // 0..4095 16B units
        int row = u >> 6;               // 0..63
        int ku  = u & 63;
        int g   = tile0 + row;
        int src = idx[(g < cnt) ? g : (cnt - 1)];
        const float4* xp = (const float4*)(x + (size_t)src * DIN) + ku * 2;
        float4 v0 = __ldg(xp);
        float4 v1 = __ldg(xp + 1);
        __half2 h0 = __floats2half2_rn(v0.x, v0.y);
        __half2 h1 = __floats2half2_rn(v0.z, v0.w);
        __half2 h2 = __floats2half2_rn(v1.x, v1.y);
        __half2 h3 = __floats2half2_rn(v1.z, v1.w);
        uint4 pk;
        pk.x = *reinterpret_cast<uint32_t*>(&h0);
        pk.y = *reinterpret_cast<uint32_t*>(&h1);
        pk.z = *reinterpret_cast<uint32_t*>(&h2);
        pk.w = *reinterpret_cast<uint32_t*>(&h3);
        uint32_t off = (uint32_t)row * 1024 + (((uint32_t)ku * 16) ^ (((uint32_t)row & 7) << 4));
        *reinterpret_cast<uint4*>(smem + off) = pk;
    }
    if (tid < TILE_M) accbuf[tid] = 0.f;
    __syncthreads();   // publishes A tile + accbuf; the ONLY barrier before the end

    // ---- fragment load helpers ----
    auto loadA = [&](int kt, int ks, uint32_t* a) {
#pragma unroll
        for (int mt = 0; mt < 4; mt++) {
            int arow = mt * 16 + (lane & 15);
            uint32_t abyte = (uint32_t)(kt * 128 + ks * 32 + (lane >> 4) * 16);
            uint32_t aaddr = sb + (uint32_t)arow * 1024 +
                             (abyte ^ (((uint32_t)arow & 7) << 4));
            LDSM_X4(a[mt * 4 + 0], a[mt * 4 + 1], a[mt * 4 + 2], a[mt * 4 + 3], aaddr);
        }
    };
    auto loadB = [&](uint32_t bbase, int ks, uint32_t* b) {
        int nt0  = (lane >> 4) & 1;
        int nrow = nt0 * 8 + (lane & 7);
        uint32_t bbyte = (uint32_t)(ks * 32 + ((lane >> 3) & 1) * 16);
        uint32_t baddr = bbase + (uint32_t)nrow * 128 +
                         (bbyte ^ (((uint32_t)nrow & 7) << 4));
        uint32_t r0, r1, r2, r3;
        LDSM_X4(r0, r1, r2, r3, baddr);
        b[0] = r0; b[1] = r1; b[2] = r2; b[3] = r3;
        int nrow2 = 16 + nt0 * 8 + (lane & 7);
        uint32_t baddr2 = bbase + (uint32_t)nrow2 * 128 +
                          (bbyte ^ (((uint32_t)nrow2 & 7) << 4));
        LDSM_X4(r0, r1, r2, r3, baddr2);
        b[4] = r0; b[5] = r1; b[6] = r2; b[7] = r3;
    };

    // ---- main loop: barrier-free; ks0 fragments prefetched across kt ----
    float partial[8];
#pragma unroll
    for (int i = 0; i < 8; i++) partial[i] = 0.f;
    uint32_t afr[16];     // A frags [mt*4+q] (single buffer, reload after use)
    uint32_t bfr[2][8];   // B frags double buffer [buf][nt*2+q]

    // preload frags for t=0, ks=0 (tile 0 complete after wait_group 1 of 2 commits)
    CP_WAIT1();
    __syncwarp();
    loadA(0, 0, afr);
    loadB(wbBase, 0, bfr[0]);

    for (int n = 0; n < NCHUNKS; n++) {
        float acc[4][4][4];
#pragma unroll
        for (int mt = 0; mt < 4; mt++)
#pragma unroll
            for (int nt = 0; nt < 4; nt++)
#pragma unroll
                for (int q = 0; q < 4; q++) acc[mt][nt][q] = 0.f;

        for (int kt = 0; kt < NKT; kt++) {
            int t = n * NKT + kt;
            if (t + 2 < NTILES) issueTileW(t + 2);
            else CP_COMMIT();                 // uniform group accounting
            CP_WAIT1();                       // tiles t AND t+1 complete (t+2 pending)
            __syncwarp();

            uint32_t bbase  = wbBase + (uint32_t)(t % NBUF) * WB_BYTES;
            uint32_t bbaseN = wbBase + (uint32_t)((t + 1) % NBUF) * WB_BYTES;
            // entry invariant: afr = (kt, ks0), bfr[0] = (t, ks0)
#pragma unroll
            for (int ks = 0; ks < 4; ks++) {
                int cur = ks & 1, nxt = cur ^ 1;
                if (ks < 3) loadB(bbase, ks + 1, bfr[nxt]);
#pragma unroll
                for (int mt = 0; mt < 4; mt++)
#pragma unroll
                    for (int nt = 0; nt < 4; nt++)
                        MMA16816(acc[mt][nt], &afr[mt * 4], &bfr[cur][nt * 2]);
                if (ks < 3) {
                    loadA(kt, ks + 1, afr);
                } else if (t + 1 < NTILES) {
                    // prefetch next kt's ks0 frags while last MMAs drain
                    loadB(bbaseN, 0, bfr[nxt]);   // nxt == 0 here (ks=3)
                    loadA((t + 1) & 7, 0, afr);
                }
            }
        }

        // ---- per-chunk epilogue fold: relu(d + b1) * w2 ----
        int cbase = n * NCHUNK + wid * 32;
#pragma unroll
        for (int nt = 0; nt < 4; nt++) {
            int c0 = cbase + nt * 8 + (lane & 3) * 2;
            float2 bb = __ldg((const float2*)(b1 + c0));
            float2 ww = __ldg((const float2*)(w2 + c0));
#pragma unroll
            for (int mt = 0; mt < 4; mt++) {
#pragma unroll
                for (int half = 0; half < 2; half++) {
                    float d0 = acc[mt][nt][half * 2 + 0];
                    float d1 = acc[mt][nt][half * 2 + 1];
                    partial[mt * 2 + half] += fmaxf(d0 + bb.x, 0.f) * ww.x
                                            + fmaxf(d1 + bb.y, 0.f) * ww.y;
                }
            }
        }
    }

    // ---- cross-warp combine ----
#pragma unroll
    for (int mt = 0; mt < 4; mt++) {
#pragma unroll
        for (int half = 0; half < 2; half++) {
            float s = partial[mt * 2 + half];
            s += __shfl_xor_sync(0xFFFFFFFFu, s, 1);
            s += __shfl_xor_sync(0xFFFFFFFFu, s, 2);
            if ((lane & 3) == 0) {
                int r = mt * 16 + half * 8 + (lane >> 2);
                atomicAdd(&accbuf[r], s);
            }
        }
    }
    __syncthreads();

    // ---- scatter ----
    if (tid < TILE_M) {
        int g = tile0 + tid;
        if (g < cnt) out[idx[g]] = accbuf[tid] + __ldg(b2);
    }
}

// ---------------- launch ----------------
extern "C" void kernel_launch(void* const* d_in, const int* in_sizes, int n_in,
                              void* d_out, int out_size) {
    const float* x   = (const float*)d_in[0];
    const int*   an  = (const int*)d_in[1];
    const float* cW1 = (const float*)d_in[2];
    const float* cb1 = (const float*)d_in[3];
    const float* cW2 = (const float*)d_in[4];
    const float* cb2 = (const float*)d_in[5];
    const float* hW1 = (const float*)d_in[6];
    const float* hb1 = (const float*)d_in[7];
    const float* hW2 = (const float*)d_in[8];
    const float* hb2 = (const float*)d_in[9];
    const float* oW1 = (const float*)d_in[10];
    const float* ob1 = (const float*)d_in[11];
    const float* oW2 = (const float*)d_in[12];
    const float* ob2 = (const float*)d_in[13];
    float* out = (float*)d_out;

    int n = in_sizes[0] / DIN;

    prep_kernel<<<1, 1>>>(an);
    route_kernel<<<(n + 255) / 256, 256>>>(an, n);
    convw_kernel<<<(DHID * DIN + 255) / 256, 256>>>(cW1, hW1, oW1);

    cudaFuncSetAttribute(fused_mlp_kernel,
                         cudaFuncAttributeMaxDynamicSharedMemorySize, SMEM_TOTAL);

    int tiles = (n + TILE_M - 1) / TILE_M;
    dim3 grid(tiles, 3);
    fused_mlp_kernel<<<grid, THREADS, SMEM_TOTAL>>>(
        x, out, cb1, hb1, ob1, cW2, hW2, oW2, cb2, hb2, ob2);
}